// round 3
// baseline (speedup 1.0000x reference)
#include <cuda_runtime.h>
#include <math.h>

#define B_ 4096
#define T_ 256
#define V_ 16
#define E_ 10
#define H_ 50
#define O_ 16

// sigmoid / tanh via MUFU (EX2 + RCP): ~1e-6 rel error, well under 1e-3 budget.
__device__ __forceinline__ float fast_sigmoid(float x) {
    return __fdividef(1.0f, 1.0f + __expf(-x));
}
__device__ __forceinline__ float fast_tanh(float x) {
    return fmaf(2.0f, __fdividef(1.0f, 1.0f + __expf(-2.0f * x)), -1.0f);
}

// Cooperative float4 copy: n must be divisible by 4, src 16B-aligned.
__device__ __forceinline__ void copy_f4(float* dst, const float* src, int n,
                                        int tid, int nthreads) {
    const float4* s = reinterpret_cast<const float4*>(src);
    float4* d = reinterpret_cast<float4*>(dst);
    for (int i = tid; i < (n >> 2); i += nthreads) d[i] = s[i];
}

// Only x[b, T-1] matters; output depends solely on the token value in [0,16).
// Params (13.5 KB) are staged to smem in one coalesced round trip; both compute
// phases then run out of smem. Each block builds the 16x16 table, then gathers.
__global__ __launch_bounds__(128, 1)
void dclstm_kernel(const int* __restrict__ x,
                   const float* __restrict__ emb,
                   const float* __restrict__ w1,
                   const float* __restrict__ b1,
                   const float* __restrict__ b2,
                   const float* __restrict__ w_out,
                   const float* __restrict__ b_out,
                   float* __restrict__ out)
{
    __shared__ float s_w1[4 * H_ * E_];   // 2000
    __shared__ float s_b12[4 * H_];       // 200 (b1+b2 fused)
    __shared__ float s_emb[V_ * E_];      // 160
    __shared__ float s_wout[O_ * H_];     // 800
    __shared__ float s_bout[O_];          // 16
    __shared__ float sh_h[V_][H_];        // 16 x 50
    __shared__ float table[V_ * O_];      // 16 x 16

    const int tid = threadIdx.x;
    const int row = blockIdx.x * 128 + tid;

    // Issue this row's token load first; latency hides under everything below.
    const int tok = x[row * T_ + (T_ - 1)];

    // ---- Stage params to smem (coalesced float4, one round trip) ----
    copy_f4(s_w1,   w1,    4 * H_ * E_, tid, 128);
    copy_f4(s_emb,  emb,   V_ * E_,     tid, 128);
    copy_f4(s_wout, w_out, O_ * H_,     tid, 128);
    copy_f4(s_bout, b_out, O_,          tid, 128);
    // b1 + b2 fused on load (200 floats = 50 float4)
    {
        const float4* pb1 = reinterpret_cast<const float4*>(b1);
        const float4* pb2 = reinterpret_cast<const float4*>(b2);
        float4* d = reinterpret_cast<float4*>(s_b12);
        for (int i = tid; i < H_; i += 128) {   // 4*H_/4 = 50 chunks
            float4 a = pb1[i], b = pb2[i];
            d[i] = make_float4(a.x + b.x, a.y + b.y, a.z + b.z, a.w + b.w);
        }
    }
    __syncthreads();

    // ---- Phase 1: hidden states. 16 tokens x 8 lanes. ----
    {
        const int v    = tid >> 3;
        const int lane = tid & 7;

        float xe[E_];
#pragma unroll
        for (int e = 0; e < E_; ++e) xe[e] = s_emb[v * E_ + e];

        for (int j = lane; j < H_; j += 8) {
            float pi = s_b12[j];
            float po = s_b12[100 + j];
            float pg = s_b12[150 + j];
#pragma unroll
            for (int e = 0; e < E_; ++e) {
                const float xev = xe[e];
                pi = fmaf(s_w1[(j)       * E_ + e], xev, pi);
                po = fmaf(s_w1[(100 + j) * E_ + e], xev, po);
                pg = fmaf(s_w1[(150 + j) * E_ + e], xev, pg);
            }
            const float it = fast_sigmoid(pi);
            const float ot = fast_sigmoid(po);
            const float g  = fast_tanh(pg);
            sh_h[v][j] = ot * fast_tanh(it * g);
        }
    }
    __syncthreads();

    // ---- Phase 2: projection. 256 table entries, 2 per thread. ----
#pragma unroll
    for (int r = 0; r < 2; ++r) {
        const int idx = tid + r * 128;
        const int v = idx >> 4;
        const int k = idx & 15;
        float s = s_bout[k];
#pragma unroll
        for (int j = 0; j < H_; ++j)
            s = fmaf(sh_h[v][j], s_wout[k * H_ + j], s);
        table[idx] = s;
    }
    __syncthreads();

    // ---- Phase 3: gather (token already in register) ----
    const float4* src = reinterpret_cast<const float4*>(&table[tok * O_]);
    float4* dst = reinterpret_cast<float4*>(out + row * O_);
    dst[0] = src[0];
    dst[1] = src[1];
    dst[2] = src[2];
    dst[3] = src[3];
}

extern "C" void kernel_launch(void* const* d_in, const int* in_sizes, int n_in,
                              void* d_out, int out_size)
{
    // metadata order: x, emb, w1, b1, w2, b2, w_out, b_out
    const int*   x     = (const int*)  d_in[0];
    const float* emb   = (const float*)d_in[1];
    const float* w1    = (const float*)d_in[2];
    const float* b1    = (const float*)d_in[3];
    // d_in[4] = w2 (unused by the reference)
    const float* b2    = (const float*)d_in[5];
    const float* w_out = (const float*)d_in[6];
    const float* b_out = (const float*)d_in[7];
    float* out = (float*)d_out;

    dclstm_kernel<<<B_ / 128, 128>>>(x, emb, w1, b1, b2, w_out, b_out, out);
}

// round 4
// speedup vs baseline: 1.0149x; 1.0149x over previous
#include <cuda_runtime.h>
#include <math.h>

#define B_ 4096
#define T_ 256
#define V_ 16
#define E_ 10
#define H_ 50
#define O_ 16

#define BLOCK_ 512
#define GRID_  (B_ / BLOCK_)   // 8

// sigmoid / tanh via MUFU (EX2 + RCP): ~1e-6 rel error, well under 1e-3 budget.
__device__ __forceinline__ float fast_sigmoid(float x) {
    return __fdividef(1.0f, 1.0f + __expf(-x));
}
__device__ __forceinline__ float fast_tanh(float x) {
    return fmaf(2.0f, __fdividef(1.0f, 1.0f + __expf(-2.0f * x)), -1.0f);
}

__device__ __forceinline__ void copy_f4(float* dst, const float* src, int n,
                                        int tid, int nthreads) {
    const float4* s = reinterpret_cast<const float4*>(src);
    float4* d = reinterpret_cast<float4*>(dst);
    for (int i = tid; i < (n >> 2); i += nthreads) d[i] = s[i];
}

// Only x[b, T-1] matters; output depends solely on the token value in [0,16).
// 512 threads/block (4 warps/SMSP for latency hiding). Phase 1: 16 tokens x
// 32 lanes, <=2 hidden units per thread. Phase 2: 1 table entry per thread.
// Phase 3: 1 row gather per thread.
__global__ __launch_bounds__(BLOCK_, 1)
void dclstm_kernel(const int* __restrict__ x,
                   const float* __restrict__ emb,
                   const float* __restrict__ w1,
                   const float* __restrict__ b1,
                   const float* __restrict__ b2,
                   const float* __restrict__ w_out,
                   const float* __restrict__ b_out,
                   float* __restrict__ out)
{
    __shared__ float s_w1[4 * H_ * E_];   // 2000
    __shared__ float s_b12[4 * H_];       // 200 (b1+b2 fused)
    __shared__ float s_emb[V_ * E_];      // 160
    __shared__ float s_wout[O_ * H_];     // 800
    __shared__ float s_bout[O_];          // 16
    __shared__ float sh_h[V_][H_];        // 16 x 50
    __shared__ float table[V_ * O_];      // 16 x 16

    const int tid = threadIdx.x;
    const int row = blockIdx.x * BLOCK_ + tid;

    // Issue this row's token load first; DRAM latency hides under table compute.
    const int tok = x[row * T_ + (T_ - 1)];

    // ---- Stage params (coalesced float4; ~1 iteration per thread) ----
    copy_f4(s_w1,   w1,    4 * H_ * E_, tid, BLOCK_);
    copy_f4(s_emb,  emb,   V_ * E_,     tid, BLOCK_);
    copy_f4(s_wout, w_out, O_ * H_,     tid, BLOCK_);
    copy_f4(s_bout, b_out, O_,          tid, BLOCK_);
    {
        const float4* pb1 = reinterpret_cast<const float4*>(b1);
        const float4* pb2 = reinterpret_cast<const float4*>(b2);
        float4* d = reinterpret_cast<float4*>(s_b12);
        for (int i = tid; i < H_; i += BLOCK_) {   // 50 float4 chunks
            float4 a = pb1[i], b = pb2[i];
            d[i] = make_float4(a.x + b.x, a.y + b.y, a.z + b.z, a.w + b.w);
        }
    }
    __syncthreads();

    // ---- Phase 1: hidden states. 16 tokens x 32 lanes, <=2 units/thread ----
    {
        const int v    = tid >> 5;        // token 0..15
        const int lane = tid & 31;        // 0..31

        float xe[E_];
#pragma unroll
        for (int e = 0; e < E_; ++e) xe[e] = s_emb[v * E_ + e];

#pragma unroll
        for (int rep = 0; rep < 2; ++rep) {
            const int j = lane + rep * 32;
            if (j < H_) {
                float pi = s_b12[j];
                float po = s_b12[100 + j];
                float pg = s_b12[150 + j];
#pragma unroll
                for (int e = 0; e < E_; ++e) {
                    const float xev = xe[e];
                    pi = fmaf(s_w1[(j)       * E_ + e], xev, pi);
                    po = fmaf(s_w1[(100 + j) * E_ + e], xev, po);
                    pg = fmaf(s_w1[(150 + j) * E_ + e], xev, pg);
                }
                const float it = fast_sigmoid(pi);
                const float ot = fast_sigmoid(po);
                const float g  = fast_tanh(pg);
                sh_h[v][j] = ot * fast_tanh(it * g);
            }
        }
    }
    __syncthreads();

    // ---- Phase 2: projection. 1 entry per thread for tid < 256 ----
    if (tid < V_ * O_) {
        const int v = tid >> 4;
        const int k = tid & 15;
        float s = s_bout[k];
#pragma unroll
        for (int j = 0; j < H_; ++j)
            s = fmaf(sh_h[v][j], s_wout[k * H_ + j], s);
        table[tid] = s;
    }
    __syncthreads();

    // ---- Phase 3: gather (token already in register) ----
    const float4* src = reinterpret_cast<const float4*>(&table[tok * O_]);
    float4* dst = reinterpret_cast<float4*>(out + row * O_);
    dst[0] = src[0];
    dst[1] = src[1];
    dst[2] = src[2];
    dst[3] = src[3];
}

extern "C" void kernel_launch(void* const* d_in, const int* in_sizes, int n_in,
                              void* d_out, int out_size)
{
    // metadata order: x, emb, w1, b1, w2, b2, w_out, b_out
    const int*   x     = (const int*)  d_in[0];
    const float* emb   = (const float*)d_in[1];
    const float* w1    = (const float*)d_in[2];
    const float* b1    = (const float*)d_in[3];
    // d_in[4] = w2 (unused by the reference)
    const float* b2    = (const float*)d_in[5];
    const float* w_out = (const float*)d_in[6];
    const float* b_out = (const float*)d_in[7];
    float* out = (float*)d_out;

    dclstm_kernel<<<GRID_, BLOCK_>>>(x, emb, w1, b1, b2, w_out, b_out, out);
}